// round 5
// baseline (speedup 1.0000x reference)
#include <cuda_runtime.h>

#define CHANNELS  8
#define IN_CH     8
#define NPARAMS   169      // 80 + 64 + 8 + 8 + 8 + 1
#define H_        128
#define W_        192
#define HW_       (H_ * W_)
#define TILE_R    16       // output logit rows per block

typedef unsigned long long u64;

// ---- packed fp32x2 helpers (Blackwell) -------------------------------------
__device__ __forceinline__ u64 fma2(u64 a, u64 b, u64 c) {
    u64 d;
    asm("fma.rn.f32x2 %0, %1, %2, %3;" : "=l"(d) : "l"(a), "l"(b), "l"(c));
    return d;
}
__device__ __forceinline__ u64 pack2(float lo, float hi) {
    u64 d;
    asm("mov.b64 %0, {%1, %2};" : "=l"(d) : "f"(lo), "f"(hi));
    return d;
}
__device__ __forceinline__ void unpack2(u64 v, float& lo, float& hi) {
    asm("mov.b64 {%0, %1}, %2;" : "=f"(lo), "=f"(hi) : "l"(v));
}
__device__ __forceinline__ u64 relu2(u64 v) {
    float lo, hi;
    unpack2(v, lo, hi);
    return pack2(fmaxf(lo, 0.0f), fmaxf(hi, 0.0f));
}

// ---------------------------------------------------------------------------
// Fused kernel. One block = (one instance) x (16-row logit tile).
// Phase 1: MLP for 17 logit rows (1 halo row above, clamped) into shared mem.
//          4 px per thread-iteration (2x f32x2 lanes) -- the lean round-2 body.
// Phase 2: aligned 2x bilinear upsample straight from shared mem to gmem.
//   O[2r,  2c  ] = 0.25*(L[r-1,c-1] + L[r-1,c] + L[r,c-1] + L[r,c])
//   O[2r,  2c+1] = 0.5 *(L[r-1,c]   + L[r,c])
//   O[2r+1,2c  ] = 0.5 *(L[r,c-1]   + L[r,c])
//   O[2r+1,2c+1] =       L[r,c]          (r-1, c-1 clamped at 0)
// ---------------------------------------------------------------------------
__global__ __launch_bounds__(256, 2)
void fused_mask_kernel(const float* __restrict__ mask_feats,   // (N, 8, H, W)
                       const float* __restrict__ params,       // (n_inst, 169)
                       const float* __restrict__ inst_loc,     // (n_inst, 2)
                       const float* __restrict__ soi_tab,      // (6,)
                       const int*   __restrict__ im_inds,      // (n_inst,)
                       const int*   __restrict__ fpn_levels,   // (n_inst,)
                       float*       __restrict__ out)
{
    __shared__ __align__(16) float2 sp2[NPARAMS];           // duplicated weights
    __shared__ __align__(16) float  st[(TILE_R + 1) * W_];  // logit tile + halo
    __shared__ float s_ix, s_iy, s_isoi;
    __shared__ int   s_im;

    const int n   = blockIdx.y;                 // instance
    const int r0  = blockIdx.x * TILE_R;        // first output logit row
    const int tid = threadIdx.x;

    for (int i = tid; i < NPARAMS; i += 256) {
        float v = params[(size_t)n * NPARAMS + i];
        sp2[i] = make_float2(v, v);
    }
    if (tid == 0) {
        s_ix   = inst_loc[2 * n + 0];
        s_iy   = inst_loc[2 * n + 1];
        s_isoi = 1.0f / soi_tab[fpn_levels[n]];
        s_im   = im_inds[n];
    }
    __syncthreads();

    const u64*  prm = reinterpret_cast<const u64*>(sp2);
    const float ix = s_ix, iy = s_iy, s = s_isoi;
    const float* featbase = mask_feats + (size_t)s_im * IN_CH * HW_;

    // ---------------- Phase 1: MLP into shared tile -------------------------
    // units: 17 rows x 48 strips of 4 px = 816  (256 threads -> 3-4 iters)
    #pragma unroll 1
    for (int u = tid; u < (TILE_R + 1) * (W_ / 4); u += 256) {
        const int row = u / (W_ / 4);
        const int c0  = (u % (W_ / 4)) * 4;
        const int gr  = max(r0 + row - 1, 0);

        const float dx  = ix - ((float)c0 * 8.0f + 4.0f);
        const float ryv = (iy - ((float)gr * 8.0f + 4.0f)) * s;
        const u64 rx01 = pack2(dx * s,           (dx - 8.0f)  * s);
        const u64 rx23 = pack2((dx - 16.0f) * s, (dx - 24.0f) * s);
        const u64 ry   = pack2(ryv, ryv);

        const float4* f4 = reinterpret_cast<const float4*>(
            featbase + (size_t)gr * W_ + c0);
        u64 fp01[IN_CH], fp23[IN_CH];
        #pragma unroll
        for (int c = 0; c < IN_CH; c++) {
            float4 v = f4[c * (HW_ / 4)];
            fp01[c] = pack2(v.x, v.y);
            fp23[c] = pack2(v.z, v.w);
        }

        // layer 0: 8 x 10, ReLU
        u64 h01[CHANNELS], h23[CHANNELS];
        #pragma unroll
        for (int o = 0; o < CHANNELS; o++) {
            u64 b  = prm[152 + o];
            u64 wx = prm[o * 10 + 0];
            u64 wy = prm[o * 10 + 1];
            u64 a0 = fma2(wy, ry, b);
            u64 a1 = a0;
            a0 = fma2(wx, rx01, a0);  a1 = fma2(wx, rx23, a1);
            #pragma unroll
            for (int c = 0; c < IN_CH; c++) {
                u64 w = prm[o * 10 + 2 + c];
                a0 = fma2(w, fp01[c], a0);
                a1 = fma2(w, fp23[c], a1);
            }
            h01[o] = relu2(a0);
            h23[o] = relu2(a1);
        }

        // layer 1 (ReLU) with layer 2 fused
        u64 acc0 = prm[168], acc1 = prm[168];
        #pragma unroll
        for (int o = 0; o < CHANNELS; o++) {
            u64 b1 = prm[160 + o];
            u64 a0 = b1, a1 = b1;
            #pragma unroll
            for (int c = 0; c < CHANNELS; c++) {
                u64 w = prm[80 + o * 8 + c];
                a0 = fma2(w, h01[c], a0);
                a1 = fma2(w, h23[c], a1);
            }
            u64 w2 = prm[144 + o];
            acc0 = fma2(w2, relu2(a0), acc0);
            acc1 = fma2(w2, relu2(a1), acc1);
        }

        float o0, o1, o2, o3;
        unpack2(acc0, o0, o1);
        unpack2(acc1, o2, o3);
        *reinterpret_cast<float4*>(st + row * W_ + c0) =
            make_float4(o0, o1, o2, o3);
    }

    __syncthreads();

    // ---------------- Phase 2: upsample from shared tile --------------------
    // units: 16 rows x 48 strips of 4 input px = 768 (= exactly 3 per thread)
    #pragma unroll 1
    for (int u = tid; u < TILE_R * (W_ / 4); u += 256) {
        const int lr = u / (W_ / 4);          // local output row
        const int c0 = (u % (W_ / 4)) * 4;
        const int r  = r0 + lr;               // global logit row

        const float* top = st + lr * W_;        // L[r-1] (halo-shifted)
        const float* bot = st + (lr + 1) * W_;  // L[r]

        const float4 A = *reinterpret_cast<const float4*>(top + c0);
        const float4 B = *reinterpret_cast<const float4*>(bot + c0);
        const float aL = (c0 == 0) ? A.x : top[c0 - 1];
        const float bL = (c0 == 0) ? B.x : bot[c0 - 1];

        const float sL = aL + bL;
        const float s0 = A.x + B.x;
        const float s1 = A.y + B.y;
        const float s2 = A.z + B.z;
        const float s3 = A.w + B.w;

        float4 r0a, r0b, r1a, r1b;
        r0a.x = 0.25f * (sL + s0);  r0a.y = 0.5f * s0;
        r0a.z = 0.25f * (s0 + s1);  r0a.w = 0.5f * s1;
        r0b.x = 0.25f * (s1 + s2);  r0b.y = 0.5f * s2;
        r0b.z = 0.25f * (s2 + s3);  r0b.w = 0.5f * s3;

        r1a.x = 0.5f * (bL + B.x);  r1a.y = B.x;
        r1a.z = 0.5f * (B.x + B.y); r1a.w = B.y;
        r1b.x = 0.5f * (B.y + B.z); r1b.y = B.z;
        r1b.z = 0.5f * (B.z + B.w); r1b.w = B.w;

        float* o = out + (size_t)n * (4 * HW_) + (size_t)(2 * r) * (2 * W_) + 2 * c0;
        reinterpret_cast<float4*>(o)[0]          = r0a;
        reinterpret_cast<float4*>(o)[1]          = r0b;
        reinterpret_cast<float4*>(o + 2 * W_)[0] = r1a;
        reinterpret_cast<float4*>(o + 2 * W_)[1] = r1b;
    }
}

// ---------------------------------------------------------------------------
extern "C" void kernel_launch(void* const* d_in, const int* in_sizes, int n_in,
                              void* d_out, int out_size)
{
    const float* mask_feats = (const float*)d_in[0];
    const float* params     = (const float*)d_in[1];
    const float* inst_loc   = (const float*)d_in[2];
    const float* soi_tab    = (const float*)d_in[3];
    const int*   im_inds    = (const int*)d_in[4];
    const int*   fpn_levels = (const int*)d_in[5];
    float*       out        = (float*)d_out;

    const int n_inst = in_sizes[1] / NPARAMS;   // 128

    dim3 grid(H_ / TILE_R, n_inst);             // 8 x 128 = 1024 blocks
    fused_mask_kernel<<<grid, 256>>>(mask_feats, params, inst_loc, soi_tab,
                                     im_inds, fpn_levels, out);
}

// round 6
// speedup vs baseline: 2.4819x; 2.4819x over previous
#include <cuda_runtime.h>

#define CHANNELS  8
#define IN_CH     8
#define NPARAMS   169      // 80 + 64 + 8 + 8 + 8 + 1
#define PSTRIDE   170      // padded (even) per-instance param stride, u64 units
#define H_        128
#define W_        192
#define HW_       (H_ * W_)
#define GI        4        // instances per block in the head kernel
#define MAX_INST  128

// Logits scratch: 128 * 24576 * 4B = 12.6 MB (L2-resident on GB300)
__device__ float g_logits[MAX_INST * HW_];

typedef unsigned long long u64;

// ---- packed fp32x2 helpers (Blackwell) -------------------------------------
__device__ __forceinline__ u64 fma2(u64 a, u64 b, u64 c) {
    u64 d;
    asm("fma.rn.f32x2 %0, %1, %2, %3;" : "=l"(d) : "l"(a), "l"(b), "l"(c));
    return d;
}
__device__ __forceinline__ u64 pack2(float lo, float hi) {
    u64 d;
    asm("mov.b64 %0, {%1, %2};" : "=l"(d) : "f"(lo), "f"(hi));
    return d;
}
__device__ __forceinline__ void unpack2(u64 v, float& lo, float& hi) {
    asm("mov.b64 {%0, %1}, %2;" : "=f"(lo), "=f"(hi) : "l"(v));
}
__device__ __forceinline__ u64 relu2(u64 v) {
    float lo, hi;
    unpack2(v, lo, hi);
    return pack2(fmaxf(lo, 0.0f), fmaxf(hi, 0.0f));
}

// ---------------------------------------------------------------------------
// Kernel 1: dynamic mask head MLP (round-2 proven shape).
// One thread = 4 consecutive pixels (2x f32x2), GI instances per block.
// Weights staged duplicated (float2{w,w}) at an EVEN u64 stride so the inner
// loops can read weight PAIRS as one LDS.128 (halves weight-load issues).
// ---------------------------------------------------------------------------
__global__ __launch_bounds__(256, 3)
void mask_head_kernel(const float* __restrict__ mask_feats,   // (N, 8, H, W)
                      const float* __restrict__ params,       // (n_inst, 169)
                      const float* __restrict__ inst_loc,     // (n_inst, 2)
                      const float* __restrict__ soi_tab,      // (6,)
                      const int*   __restrict__ im_inds,      // (n_inst,)
                      const int*   __restrict__ fpn_levels,   // (n_inst,)
                      int n_inst)
{
    __shared__ __align__(16) float2 sp2[GI * PSTRIDE];
    __shared__ float  s_ix[GI], s_iy[GI], s_isoi[GI];
    __shared__ int    s_im[GI];

    const int n0  = blockIdx.y * GI;
    const int tid = threadIdx.x;

    const int g_cnt = min(GI, n_inst - n0);
    #pragma unroll 1
    for (int g = 0; g < g_cnt; g++)
        for (int i = tid; i < NPARAMS; i += 256) {
            float v = params[(size_t)(n0 + g) * NPARAMS + i];
            sp2[g * PSTRIDE + i] = make_float2(v, v);
        }
    if (tid < GI && n0 + tid < n_inst) {
        int n = n0 + tid;
        s_ix[tid]   = inst_loc[2 * n + 0];
        s_iy[tid]   = inst_loc[2 * n + 1];
        s_isoi[tid] = 1.0f / soi_tab[fpn_levels[n]];
        s_im[tid]   = im_inds[n];
    }
    __syncthreads();

    const int p0 = (blockIdx.x * 256 + tid) * 4;   // 4 consecutive px, same row
    const int px = p0 % W_;
    const int py = p0 / W_;
    const float lx0 = (float)px * 8.0f + 4.0f;     // MASK_FEAT_STRIDE = 8
    const float ly  = (float)py * 8.0f + 4.0f;

    #pragma unroll 1
    for (int g = 0; g < g_cnt; g++) {
        const u64* prm = reinterpret_cast<const u64*>(sp2) + g * PSTRIDE;

        const float s  = s_isoi[g];
        const float dx = s_ix[g] - lx0;
        const float ryv = (s_iy[g] - ly) * s;
        const u64 rx01 = pack2(dx * s,           (dx - 8.0f)  * s);
        const u64 rx23 = pack2((dx - 16.0f) * s, (dx - 24.0f) * s);
        const u64 ry   = pack2(ryv, ryv);

        const float4* f4 = reinterpret_cast<const float4*>(
            mask_feats + (size_t)s_im[g] * IN_CH * HW_ + p0);
        u64 fp01[IN_CH], fp23[IN_CH];
        #pragma unroll
        for (int c = 0; c < IN_CH; c++) {
            float4 v = f4[c * (HW_ / 4)];
            fp01[c] = pack2(v.x, v.y);
            fp23[c] = pack2(v.z, v.w);
        }

        // layer 0: 8 x 10, ReLU  (weights read as LDS.128 pairs)
        u64 h01[CHANNELS], h23[CHANNELS];
        #pragma unroll
        for (int o = 0; o < CHANNELS; o++) {
            ulonglong2 wxy =
                *reinterpret_cast<const ulonglong2*>(prm + o * 10);  // wx, wy
            u64 b  = prm[152 + o];
            u64 a0 = fma2(wxy.y, ry, b);
            u64 a1 = a0;
            a0 = fma2(wxy.x, rx01, a0);  a1 = fma2(wxy.x, rx23, a1);
            #pragma unroll
            for (int c = 0; c < IN_CH; c += 2) {
                ulonglong2 w =
                    *reinterpret_cast<const ulonglong2*>(prm + o * 10 + 2 + c);
                a0 = fma2(w.x, fp01[c],     a0);
                a1 = fma2(w.x, fp23[c],     a1);
                a0 = fma2(w.y, fp01[c + 1], a0);
                a1 = fma2(w.y, fp23[c + 1], a1);
            }
            h01[o] = relu2(a0);
            h23[o] = relu2(a1);
        }

        // layer 1 (ReLU) with layer 2 fused
        u64 acc0 = prm[168], acc1 = prm[168];
        #pragma unroll
        for (int o = 0; o < CHANNELS; o++) {
            u64 b1 = prm[160 + o];
            u64 a0 = b1, a1 = b1;
            #pragma unroll
            for (int c = 0; c < CHANNELS; c += 2) {
                ulonglong2 w =
                    *reinterpret_cast<const ulonglong2*>(prm + 80 + o * 8 + c);
                a0 = fma2(w.x, h01[c],     a0);
                a1 = fma2(w.x, h23[c],     a1);
                a0 = fma2(w.y, h01[c + 1], a0);
                a1 = fma2(w.y, h23[c + 1], a1);
            }
            u64 w2 = prm[144 + o];
            acc0 = fma2(w2, relu2(a0), acc0);
            acc1 = fma2(w2, relu2(a1), acc1);
        }

        float o0, o1, o2, o3;
        unpack2(acc0, o0, o1);
        unpack2(acc1, o2, o3);
        *reinterpret_cast<float4*>(g_logits + (size_t)(n0 + g) * HW_ + p0) =
            make_float4(o0, o1, o2, o3);
    }
}

// ---------------------------------------------------------------------------
// Kernel 2: aligned 2x bilinear upsample (round-2 unit shape, 2 units/thread,
// all 12 loads batched before compute to hide L2 latency).
//   O[2r,  2c  ] = 0.25*(L[r-1,c-1] + L[r-1,c] + L[r,c-1] + L[r,c])
//   O[2r,  2c+1] = 0.5 *(L[r-1,c]   + L[r,c])
//   O[2r+1,2c  ] = 0.5 *(L[r,c-1]   + L[r,c])
//   O[2r+1,2c+1] =       L[r,c]          (r-1, c-1 clamped at 0)
// ---------------------------------------------------------------------------
__device__ __forceinline__ void up_compute_store(
    float* __restrict__ out, int n, int r, int c2,
    float tm, float2 t01, float um, float2 u01)
{
    float2 row0 = make_float2(0.25f * ((tm + t01.x) + (um + u01.x)),
                              0.5f  * (t01.x + u01.x));
    float2 row1 = make_float2(0.5f  * (um + u01.x), u01.x);
    // second output column pair folds into the same float2 stores:
    // outputs at columns 2c..2c+1 handled here; the unit covers 2 input px
    // -> 4 output cols, stored as two float2 pairs below by caller pattern.
    (void)row0; (void)row1; (void)t01; (void)u01; (void)out; (void)n; (void)r; (void)c2;
}

__global__ __launch_bounds__(256)
void upsample_kernel(float* __restrict__ out, int n_inst)
{
    const int total = n_inst * (HW_ / 2);
    const int i0 = blockIdx.x * 512 + threadIdx.x;
    const int i1 = i0 + 256;
    if (i0 >= total) return;

    // ---- decode + batched loads for unit A ----
    const int c2a = i0 % (W_ / 2);
    const int ra  = (i0 / (W_ / 2)) % H_;
    const int na  = i0 / (HW_ / 2);
    const float* La = g_logits + (size_t)na * HW_;
    const int c0a = 2 * c2a;
    const int cma = max(c0a - 1, 0);
    const int rma = max(ra - 1, 0);
    const float  tma  = La[rma * W_ + cma];
    const float2 t01a = *reinterpret_cast<const float2*>(La + rma * W_ + c0a);
    const float  uma  = La[ra * W_ + cma];
    const float2 u01a = *reinterpret_cast<const float2*>(La + ra * W_ + c0a);

    const bool haveB = (i1 < total);
    // ---- decode + batched loads for unit B ----
    int c2b = 0, rb = 0, nb = 0, c0b = 0;
    float tmb = 0.f, umb = 0.f;
    float2 t01b = make_float2(0.f, 0.f), u01b = make_float2(0.f, 0.f);
    if (haveB) {
        c2b = i1 % (W_ / 2);
        rb  = (i1 / (W_ / 2)) % H_;
        nb  = i1 / (HW_ / 2);
        const float* Lb = g_logits + (size_t)nb * HW_;
        c0b = 2 * c2b;
        const int cmb = max(c0b - 1, 0);
        const int rmb = max(rb - 1, 0);
        tmb  = Lb[rmb * W_ + cmb];
        t01b = *reinterpret_cast<const float2*>(Lb + rmb * W_ + c0b);
        umb  = Lb[rb * W_ + cmb];
        u01b = *reinterpret_cast<const float2*>(Lb + rb * W_ + c0b);
    }

    // ---- compute + store unit A ----
    {
        float4 r0, r1;
        r0.x = 0.25f * ((tma + t01a.x) + (uma + u01a.x));
        r0.y = 0.5f  * (t01a.x + u01a.x);
        r0.z = 0.25f * ((t01a.x + t01a.y) + (u01a.x + u01a.y));
        r0.w = 0.5f  * (t01a.y + u01a.y);
        r1.x = 0.5f  * (uma + u01a.x);
        r1.y = u01a.x;
        r1.z = 0.5f  * (u01a.x + u01a.y);
        r1.w = u01a.y;
        float* o = out + (size_t)na * (4 * HW_) + (size_t)(2 * ra) * (2 * W_) + 2 * c0a;
        *reinterpret_cast<float4*>(o)          = r0;
        *reinterpret_cast<float4*>(o + 2 * W_) = r1;
    }
    // ---- compute + store unit B ----
    if (haveB) {
        float4 r0, r1;
        r0.x = 0.25f * ((tmb + t01b.x) + (umb + u01b.x));
        r0.y = 0.5f  * (t01b.x + u01b.x);
        r0.z = 0.25f * ((t01b.x + t01b.y) + (u01b.x + u01b.y));
        r0.w = 0.5f  * (t01b.y + u01b.y);
        r1.x = 0.5f  * (umb + u01b.x);
        r1.y = u01b.x;
        r1.z = 0.5f  * (u01b.x + u01b.y);
        r1.w = u01b.y;
        float* o = out + (size_t)nb * (4 * HW_) + (size_t)(2 * rb) * (2 * W_) + 2 * c0b;
        *reinterpret_cast<float4*>(o)          = r0;
        *reinterpret_cast<float4*>(o + 2 * W_) = r1;
    }
}

// ---------------------------------------------------------------------------
extern "C" void kernel_launch(void* const* d_in, const int* in_sizes, int n_in,
                              void* d_out, int out_size)
{
    const float* mask_feats = (const float*)d_in[0];
    const float* params     = (const float*)d_in[1];
    const float* inst_loc   = (const float*)d_in[2];
    const float* soi_tab    = (const float*)d_in[3];
    const int*   im_inds    = (const int*)d_in[4];
    const int*   fpn_levels = (const int*)d_in[5];
    float*       out        = (float*)d_out;

    const int n_inst = in_sizes[1] / NPARAMS;   // 128

    dim3 grid1(HW_ / (256 * 4), (n_inst + GI - 1) / GI);   // 24 x 32
    mask_head_kernel<<<grid1, 256>>>(mask_feats, params, inst_loc, soi_tab,
                                     im_inds, fpn_levels, n_inst);

    const int total = n_inst * (HW_ / 2);
    upsample_kernel<<<(total + 511) / 512, 256>>>(out, n_inst);
}